// round 8
// baseline (speedup 1.0000x reference)
#include <cuda_runtime.h>
#include <cuda_bf16.h>
#include <cstdint>

#define D 256
#define BT 2048   // B*T
#define KS 512    // stored K per row: [hi(256) | lo(256)]
#define NST 4     // cp.async pipeline stages

// Scratch (static device globals — no allocation).
__device__ float g_Q[BT * D];
__device__ float g_K[BT * D];
__device__ float g_V[BT * D];
__device__ __nv_bfloat16 g_Ap[BT * KS];       // split X  [hi|lo]
__device__ __nv_bfloat16 g_Wp[3][D * KS];     // split Wq/Wk/Wv [hi|lo]

// ---------------------------------------------------------------------------
// helpers
// ---------------------------------------------------------------------------
__device__ __forceinline__ uint32_t smem_u32(const void* p) {
    uint32_t a;
    asm("{ .reg .u64 t; cvta.to.shared.u64 t, %1; cvt.u32.u64 %0, t; }"
        : "=r"(a) : "l"(p));
    return a;
}
__device__ __forceinline__ void ldm_x4(uint32_t& r0, uint32_t& r1,
                                       uint32_t& r2, uint32_t& r3, uint32_t a) {
    asm volatile("ldmatrix.sync.aligned.m8n8.x4.shared.b16 {%0,%1,%2,%3}, [%4];"
                 : "=r"(r0), "=r"(r1), "=r"(r2), "=r"(r3) : "r"(a));
}
__device__ __forceinline__ void mma16816(float* c, const uint32_t* a,
                                         const uint32_t* b) {
    asm volatile(
        "mma.sync.aligned.m16n8k16.row.col.f32.bf16.bf16.f32 "
        "{%0,%1,%2,%3}, {%4,%5,%6,%7}, {%8,%9}, {%0,%1,%2,%3};"
        : "+f"(c[0]), "+f"(c[1]), "+f"(c[2]), "+f"(c[3])
        : "r"(a[0]), "r"(a[1]), "r"(a[2]), "r"(a[3]), "r"(b[0]), "r"(b[1]));
}
__device__ __forceinline__ void cpa16(uint32_t s, const void* g) {
    asm volatile("cp.async.cg.shared.global [%0], [%1], 16;"
                 :: "r"(s), "l"(g) : "memory");
}
#define CP_COMMIT() asm volatile("cp.async.commit_group;" ::: "memory")
#define CP_WAIT2()  asm volatile("cp.async.wait_group 2;" ::: "memory")

// 64B rows, 4 x 16B chunks, XOR swizzle: chunk ^= (row>>1)&3.
#define SWOFF(row, c) ((row) * 64 + ((((c) ^ (((row) >> 1) & 3))) << 4))

struct __align__(8) bf16x4 { __nv_bfloat162 a, b; };

// ---------------------------------------------------------------------------
// Split-precision conversion (R6 version): one float4 per thread, 8B stores.
// Threads [0, 131072) convert X; [131072, 180224) convert W.
// ---------------------------------------------------------------------------
__global__ __launch_bounds__(256) void convert_all(
    const float4* __restrict__ X4,
    const float4* __restrict__ Wq4,
    const float4* __restrict__ Wk4,
    const float4* __restrict__ Wv4)
{
    const int gid = blockIdx.x * 256 + threadIdx.x;
    float4 x;
    __nv_bfloat16* hp;
    if (gid < BT * D / 4) {
        const int t = gid >> 6;            // 64 float4 per row
        const int d = (gid & 63) * 4;
        x = X4[gid];
        hp = &g_Ap[t * KS + d];
    } else {
        const int g = gid - BT * D / 4;    // < 49152
        const int z = g >> 14;             // 16384 float4 per matrix
        const int r = g & 16383;
        const int i = r >> 6;
        const int d = (r & 63) * 4;
        const float4* W4 = (z == 0) ? Wq4 : (z == 1) ? Wk4 : Wv4;
        x = W4[r];
        hp = &g_Wp[z][i * KS + d];
    }
    __nv_bfloat16 h0 = __float2bfloat16_rn(x.x);
    __nv_bfloat16 h1 = __float2bfloat16_rn(x.y);
    __nv_bfloat16 h2 = __float2bfloat16_rn(x.z);
    __nv_bfloat16 h3 = __float2bfloat16_rn(x.w);
    bf16x4 hi, lo;
    hi.a = __nv_bfloat162(h0, h1);
    hi.b = __nv_bfloat162(h2, h3);
    lo.a = __nv_bfloat162(__float2bfloat16_rn(x.x - __bfloat162float(h0)),
                          __float2bfloat16_rn(x.y - __bfloat162float(h1)));
    lo.b = __nv_bfloat162(__float2bfloat16_rn(x.z - __bfloat162float(h2)),
                          __float2bfloat16_rn(x.w - __bfloat162float(h3)));
    *(bf16x4*)hp         = hi;
    *(bf16x4*)(hp + 256) = lo;
}

// ---------------------------------------------------------------------------
// bf16 mma.sync GEMM, 128x128 CTA tiles, 256 threads (8 warps), K-step 32,
// 4-stage cp.async, dynamic smem 64KB. Grid 16 x 2 x 3 = 96 CTAs.
// K-tile sets (32-wide):
//   z==2 (V): 24 tiles: kt=0..23  -> Ahi*Bhi + Alo*Bhi + Ahi*Blo
//   z<2 (Q,K): 16 tiles: kt in {0..7, 16..23} -> Ahi*Bhi + Ahi*Blo
//     (drops Alo*Bhi; x-lo kept is the larger correction -> err ~1e-4)
// Mapping: akt = kt & 15 ; bkt = kt<8 ? kt : kt-8.
// ---------------------------------------------------------------------------
__global__ __launch_bounds__(256) void mma_gemm(
    const float* __restrict__ bq, const float* __restrict__ bk,
    const float* __restrict__ bv)
{
    extern __shared__ __align__(16) char smem[];
    char* sAm = smem;                      // NST * 8KB
    char* sBm = smem + NST * 8192;         // NST * 8KB

    const int tid  = threadIdx.x;
    const int lane = tid & 31;
    const int wid  = tid >> 5;
    const int warp_m = wid & 3;            // 4 x 32 = 128 M
    const int warp_n = wid >> 2;           // 2 x 64 = 128 N

    const int row0 = blockIdx.x * 128;
    const int col0 = blockIdx.y * 128;
    const int z    = blockIdx.z;
    const float* bias = (z == 0) ? bq : (z == 1) ? bk : bv;
    float* Cw = (z == 0) ? g_Q : (z == 1) ? g_K : g_V;
    const int kmax = (z == 2) ? 24 : 16;

    const __nv_bfloat16* Ag = g_Ap;
    const __nv_bfloat16* Bg = g_Wp[z];

    // loader: thread -> (row 0..127, 2 x 16B chunks)
    const int lrow  = tid >> 1;
    const int cbase = (tid & 1) * 2;
    const __nv_bfloat16* agp = Ag + (size_t)(row0 + lrow) * KS + cbase * 8;
    const __nv_bfloat16* bgp = Bg + (size_t)(col0 + lrow) * KS + cbase * 8;
    const uint32_t sA_base = smem_u32(sAm);
    const uint32_t sB_base = smem_u32(sBm);
    uint32_t saoff[2], sboff[2];
    #pragma unroll
    for (int j = 0; j < 2; j++) {
        saoff[j] = sA_base + SWOFF(lrow, cbase + j);
        sboff[j] = sB_base + SWOFF(lrow, cbase + j);
    }

    // ldmatrix fragment addresses
    uint32_t aaddr[2][2], baddr[4][2];
    {
        const int m = lane >> 3;
        const int ar  = ((m & 1) << 3) + (lane & 7);
        const int akc = m >> 1;
        const int bn  = ((m >> 1) << 3) + (lane & 7);
        const int bkc = m & 1;
        #pragma unroll
        for (int f = 0; f < 2; f++) {
            const int row = warp_m * 32 + f * 16 + ar;
            #pragma unroll
            for (int h = 0; h < 2; h++)
                aaddr[f][h] = sA_base + SWOFF(row, akc + 2 * h);
        }
        #pragma unroll
        for (int g = 0; g < 4; g++) {
            const int row = warp_n * 64 + g * 16 + bn;
            #pragma unroll
            for (int h = 0; h < 2; h++)
                baddr[g][h] = sB_base + SWOFF(row, bkc + 2 * h);
        }
    }

    float acc[2][8][4];
    #pragma unroll
    for (int f = 0; f < 2; f++)
        #pragma unroll
        for (int g = 0; g < 8; g++)
            #pragma unroll
            for (int i = 0; i < 4; i++) acc[f][g][i] = 0.f;

    // K-tile index map: i-th executed tile -> logical kt
    //   z==2: kt = i ; z<2: kt = (i<8)? i : i+8
    // prologue: stages 0..2
    #pragma unroll
    for (int st = 0; st < NST - 1; st++) {
        const int kt  = (z == 2) ? st : ((st < 8) ? st : st + 8);
        const int akt = kt & 15;
        const int bkt = (kt < 8) ? kt : kt - 8;
        const uint32_t so = st * 8192;
        #pragma unroll
        for (int j = 0; j < 2; j++) {
            cpa16(saoff[j] + so, agp + akt * 32 + j * 8);
            cpa16(sboff[j] + so, bgp + bkt * 32 + j * 8);
        }
        CP_COMMIT();
    }

    for (int it = 0; it < kmax; it++) {
        CP_WAIT2();
        __syncthreads();

        const int nst = it + NST - 1;
        if (nst < kmax) {
            const int kt  = (z == 2) ? nst : ((nst < 8) ? nst : nst + 8);
            const int akt = kt & 15;
            const int bkt = (kt < 8) ? kt : kt - 8;
            const uint32_t so = (nst & (NST - 1)) * 8192;
            #pragma unroll
            for (int j = 0; j < 2; j++) {
                cpa16(saoff[j] + so, agp + akt * 32 + j * 8);
                cpa16(sboff[j] + so, bgp + bkt * 32 + j * 8);
            }
        }
        CP_COMMIT();

        const uint32_t so = (it & (NST - 1)) * 8192;
        #pragma unroll
        for (int h = 0; h < 2; h++) {
            uint32_t af[2][4], bfr[4][4];
            ldm_x4(af[0][0], af[0][1], af[0][2], af[0][3], aaddr[0][h] + so);
            ldm_x4(af[1][0], af[1][1], af[1][2], af[1][3], aaddr[1][h] + so);
            #pragma unroll
            for (int g = 0; g < 4; g++)
                ldm_x4(bfr[g][0], bfr[g][1], bfr[g][2], bfr[g][3],
                       baddr[g][h] + so);
            #pragma unroll
            for (int f = 0; f < 2; f++) {
                #pragma unroll
                for (int g = 0; g < 4; g++) {
                    mma16816(acc[f][2 * g + 0], af[f], &bfr[g][0]);
                    mma16816(acc[f][2 * g + 1], af[f], &bfr[g][2]);
                }
            }
        }
    }

    // epilogue: add bias, store fp32
    const int tg = lane >> 2;
    const int tc = (lane & 3) * 2;
    #pragma unroll
    for (int f = 0; f < 2; f++) {
        const int rbase = row0 + warp_m * 32 + f * 16 + tg;
        #pragma unroll
        for (int g = 0; g < 8; g++) {
            const int c = col0 + warp_n * 64 + g * 8 + tc;
            const float b0 = bias[c], b1 = bias[c + 1];
            float2 v0 = { acc[f][g][0] + b0, acc[f][g][1] + b1 };
            float2 v1 = { acc[f][g][2] + b0, acc[f][g][3] + b1 };
            *(float2*)&Cw[(size_t)rbase * D + c]       = v0;
            *(float2*)&Cw[(size_t)(rbase + 8) * D + c] = v1;
        }
    }
}

// ---------------------------------------------------------------------------
// Attention via rank-13 Taylor factorization of exp(q*k/16).
// One warp per token; lane owns 8 CONTIGUOUS elements (float4 loads/stores).
// ---------------------------------------------------------------------------
__global__ __launch_bounds__(128) void attn_kernel(float* __restrict__ out)
{
    const int lane = threadIdx.x & 31;
    const int t = blockIdx.x * 4 + (threadIdx.x >> 5);
    const int base = t * D;
    const int eb = base + lane * 8;
    const float s = 1.0f / 16.0f;

    float4 k4a = *(const float4*)&g_K[eb];
    float4 k4b = *(const float4*)&g_K[eb + 4];
    float4 v4a = *(const float4*)&g_V[eb];
    float4 v4b = *(const float4*)&g_V[eb + 4];
    float4 q4a = *(const float4*)&g_Q[eb];
    float4 q4b = *(const float4*)&g_Q[eb + 4];

    float kv[8] = { k4a.x * s, k4a.y * s, k4a.z * s, k4a.w * s,
                    k4b.x * s, k4b.y * s, k4b.z * s, k4b.w * s };
    float vv[8] = { v4a.x, v4a.y, v4a.z, v4a.w, v4b.x, v4b.y, v4b.z, v4b.w };
    float qv[8] = { q4a.x, q4a.y, q4a.z, q4a.w, q4b.x, q4b.y, q4b.z, q4b.w };

    float m[13], M[13];
    #pragma unroll
    for (int n = 0; n < 13; n++) { m[n] = 0.f; M[n] = 0.f; }
    #pragma unroll
    for (int u = 0; u < 8; u++) {
        const float k1 = kv[u], v1 = vv[u];
        M[0] += v1;
        float kp = k1;
        m[1] += kp; M[1] += kp * v1;
        #pragma unroll
        for (int n = 2; n <= 12; n++) {
            kp *= k1;
            m[n] += kp;
            M[n] += kp * v1;
        }
    }
    m[0] = 8.0f;

    #pragma unroll
    for (int off = 16; off; off >>= 1) {
        #pragma unroll
        for (int n = 0; n < 13; n++) {
            m[n] += __shfl_xor_sync(0xFFFFFFFFu, m[n], off);
            M[n] += __shfl_xor_sync(0xFFFFFFFFu, M[n], off);
        }
    }

    const float invf[13] = {
        1.f, 1.f, 0.5f, 1.f/6.f, 1.f/24.f, 1.f/120.f, 1.f/720.f,
        1.f/5040.f, 1.f/40320.f, 1.f/362880.f, 1.f/3628800.f,
        1.f/39916800.f, 1.f/479001600.f };
    #pragma unroll
    for (int n = 2; n < 13; n++) { m[n] *= invf[n]; M[n] *= invf[n]; }

    float res[8];
    #pragma unroll
    for (int u = 0; u < 8; u++) {
        const float q = qv[u];
        float num = M[12], den = m[12];
        #pragma unroll
        for (int n = 11; n >= 0; n--) {
            num = num * q + M[n];
            den = den * q + m[n];
        }
        res[u] = __fdividef(num, den);
    }
    *(float4*)&out[eb]     = make_float4(res[0], res[1], res[2], res[3]);
    *(float4*)&out[eb + 4] = make_float4(res[4], res[5], res[6], res[7]);
}

// ---------------------------------------------------------------------------
// Launch. Inputs: x, Wq, bq, Wk, bk, Wv, bv. Output fp32 [2,1024,256].
// ---------------------------------------------------------------------------
extern "C" void kernel_launch(void* const* d_in, const int* in_sizes, int n_in,
                              void* d_out, int out_size)
{
    const float* x  = (const float*)d_in[0];
    const float* Wq = (const float*)d_in[1];
    const float* bq = (const float*)d_in[2];
    const float* Wk = (const float*)d_in[3];
    const float* bk = (const float*)d_in[4];
    const float* Wv = (const float*)d_in[5];
    const float* bv = (const float*)d_in[6];
    float* out = (float*)d_out;

    cudaFuncSetAttribute(mma_gemm, cudaFuncAttributeMaxDynamicSharedMemorySize,
                         NST * 16384);

    convert_all<<<704, 256>>>((const float4*)x, (const float4*)Wq,
                              (const float4*)Wk, (const float4*)Wv);
    dim3 ggrid(BT / 128, D / 128, 3);   // 16 x 2 x 3 = 96 CTAs
    mma_gemm<<<ggrid, 256, NST * 16384>>>(bq, bk, bv);
    attn_kernel<<<BT / 4, 128>>>(out);
}

// round 9
// speedup vs baseline: 1.1000x; 1.1000x over previous
#include <cuda_runtime.h>
#include <cuda_bf16.h>
#include <cstdint>

#define D 256
#define BT 2048   // B*T
#define KS 512    // stored K per row: [hi(256) | lo(256)]
#define NST 3     // cp.async pipeline stages

// Scratch (static device globals — no allocation).
__device__ float g_Q[BT * D];
__device__ float g_K[BT * D];
__device__ float g_V[BT * D];
__device__ __nv_bfloat16 g_Ap[BT * KS];       // split X  [hi|lo]
__device__ __nv_bfloat16 g_Wp[3][D * KS];     // split Wq/Wk/Wv [hi|lo]

// ---------------------------------------------------------------------------
// helpers
// ---------------------------------------------------------------------------
__device__ __forceinline__ uint32_t smem_u32(const void* p) {
    uint32_t a;
    asm("{ .reg .u64 t; cvta.to.shared.u64 t, %1; cvt.u32.u64 %0, t; }"
        : "=r"(a) : "l"(p));
    return a;
}
__device__ __forceinline__ void ldm_x4(uint32_t& r0, uint32_t& r1,
                                       uint32_t& r2, uint32_t& r3, uint32_t a) {
    asm volatile("ldmatrix.sync.aligned.m8n8.x4.shared.b16 {%0,%1,%2,%3}, [%4];"
                 : "=r"(r0), "=r"(r1), "=r"(r2), "=r"(r3) : "r"(a));
}
__device__ __forceinline__ void mma16816(float* c, const uint32_t* a,
                                         const uint32_t* b) {
    asm volatile(
        "mma.sync.aligned.m16n8k16.row.col.f32.bf16.bf16.f32 "
        "{%0,%1,%2,%3}, {%4,%5,%6,%7}, {%8,%9}, {%0,%1,%2,%3};"
        : "+f"(c[0]), "+f"(c[1]), "+f"(c[2]), "+f"(c[3])
        : "r"(a[0]), "r"(a[1]), "r"(a[2]), "r"(a[3]), "r"(b[0]), "r"(b[1]));
}
__device__ __forceinline__ void cpa16(uint32_t s, const void* g) {
    asm volatile("cp.async.cg.shared.global [%0], [%1], 16;"
                 :: "r"(s), "l"(g) : "memory");
}
#define CP_COMMIT() asm volatile("cp.async.commit_group;" ::: "memory")
#define CP_WAIT1()  asm volatile("cp.async.wait_group 1;" ::: "memory")

// 128B rows, 8 x 16B chunks, full XOR swizzle: chunk ^= row&7.
#define SWOFF2(row, c) ((row) * 128 + ((((c) ^ ((row) & 7))) << 4))

struct __align__(8) bf16x4 { __nv_bfloat162 a, b; };

// ---------------------------------------------------------------------------
// Split-precision conversion (R6 version): one float4 per thread, 8B stores.
// Threads [0, 131072) convert X; [131072, 180224) convert W.
// ---------------------------------------------------------------------------
__global__ __launch_bounds__(256) void convert_all(
    const float4* __restrict__ X4,
    const float4* __restrict__ Wq4,
    const float4* __restrict__ Wk4,
    const float4* __restrict__ Wv4)
{
    const int gid = blockIdx.x * 256 + threadIdx.x;
    float4 x;
    __nv_bfloat16* hp;
    if (gid < BT * D / 4) {
        const int t = gid >> 6;            // 64 float4 per row
        const int d = (gid & 63) * 4;
        x = X4[gid];
        hp = &g_Ap[t * KS + d];
    } else {
        const int g = gid - BT * D / 4;    // < 49152
        const int z = g >> 14;             // 16384 float4 per matrix
        const int r = g & 16383;
        const int i = r >> 6;
        const int d = (r & 63) * 4;
        const float4* W4 = (z == 0) ? Wq4 : (z == 1) ? Wk4 : Wv4;
        x = W4[r];
        hp = &g_Wp[z][i * KS + d];
    }
    __nv_bfloat16 h0 = __float2bfloat16_rn(x.x);
    __nv_bfloat16 h1 = __float2bfloat16_rn(x.y);
    __nv_bfloat16 h2 = __float2bfloat16_rn(x.z);
    __nv_bfloat16 h3 = __float2bfloat16_rn(x.w);
    bf16x4 hi, lo;
    hi.a = __nv_bfloat162(h0, h1);
    hi.b = __nv_bfloat162(h2, h3);
    lo.a = __nv_bfloat162(__float2bfloat16_rn(x.x - __bfloat162float(h0)),
                          __float2bfloat16_rn(x.y - __bfloat162float(h1)));
    lo.b = __nv_bfloat162(__float2bfloat16_rn(x.z - __bfloat162float(h2)),
                          __float2bfloat16_rn(x.w - __bfloat162float(h3)));
    *(bf16x4*)hp         = hi;
    *(bf16x4*)(hp + 256) = lo;
}

// ---------------------------------------------------------------------------
// bf16 mma.sync GEMM, 64x64 CTA tiles, 4 warps, K-step 64, 3-stage cp.async.
// Logical K-tiles (64-wide): A'=[hi|lo|hi] -> akt = kt<8 ? kt : kt-8
//                            W'=[hi|hi|lo] -> bkt = kt<4 ? kt : kt-4
// Executed tile sets:
//   z==2 (V): 12 tiles, kt = it              (full: hihi + lohi + hilo)
//   z<2 (Q,K): 8 tiles, kt = it<4? it : it+4 (drops Alo*Whi -> err ~1.3e-4)
// Grid 32 x 4 x 3 = 384 CTAs. 32 MMAs between syncs.
// ---------------------------------------------------------------------------
__global__ __launch_bounds__(128) void mma_gemm(
    const float* __restrict__ bq, const float* __restrict__ bk,
    const float* __restrict__ bv)
{
    __shared__ __align__(16) char sA[NST][64 * 128];   // 24KB
    __shared__ __align__(16) char sB[NST][64 * 128];   // 24KB

    const int tid  = threadIdx.x;
    const int lane = tid & 31;
    const int wid  = tid >> 5;
    const int warp_m = wid & 1;
    const int warp_n = wid >> 1;

    const int row0 = blockIdx.x * 64;
    const int col0 = blockIdx.y * 64;
    const int z    = blockIdx.z;
    const float* bias = (z == 0) ? bq : (z == 1) ? bk : bv;
    float* Cw = (z == 0) ? g_Q : (z == 1) ? g_K : g_V;
    const int kmax = (z == 2) ? 12 : 8;

    const __nv_bfloat16* Ag = g_Ap;
    const __nv_bfloat16* Bg = g_Wp[z];

    // loader: thread -> (row, 4 x 16B chunks)
    const int lrow  = tid >> 1;          // 0..63
    const int cbase = (tid & 1) * 4;     // 0 or 4
    const __nv_bfloat16* agp = Ag + (size_t)(row0 + lrow) * KS + cbase * 8;
    const __nv_bfloat16* bgp = Bg + (size_t)(col0 + lrow) * KS + cbase * 8;
    const uint32_t sA_base = smem_u32(sA);
    const uint32_t sB_base = smem_u32(sB);
    uint32_t saoff[4], sboff[4];
    #pragma unroll
    for (int j = 0; j < 4; j++) {
        saoff[j] = sA_base + SWOFF2(lrow, cbase + j);
        sboff[j] = sB_base + SWOFF2(lrow, cbase + j);
    }

    // ldmatrix fragment addresses: [frag][h] over 4 k16-halves
    uint32_t aaddr[2][4], baddr[2][4];
    {
        const int m = lane >> 3;
        const int ar  = ((m & 1) << 3) + (lane & 7);
        const int akc = m >> 1;
        const int bn  = ((m >> 1) << 3) + (lane & 7);
        const int bkc = m & 1;
        #pragma unroll
        for (int f = 0; f < 2; f++) {
            const int row = warp_m * 32 + f * 16 + ar;
            #pragma unroll
            for (int h = 0; h < 4; h++)
                aaddr[f][h] = sA_base + SWOFF2(row, akc + 2 * h);
        }
        #pragma unroll
        for (int g = 0; g < 2; g++) {
            const int row = warp_n * 32 + g * 16 + bn;
            #pragma unroll
            for (int h = 0; h < 4; h++)
                baddr[g][h] = sB_base + SWOFF2(row, bkc + 2 * h);
        }
    }

    float acc[2][4][4];
    #pragma unroll
    for (int f = 0; f < 2; f++)
        #pragma unroll
        for (int g = 0; g < 4; g++)
            #pragma unroll
            for (int i = 0; i < 4; i++) acc[f][g][i] = 0.f;

    // prologue: stages 0,1
    #pragma unroll
    for (int st = 0; st < NST - 1; st++) {
        const int kt  = (z == 2) ? st : ((st < 4) ? st : st + 4);
        const int akt = (kt < 8) ? kt : kt - 8;
        const int bkt = (kt < 4) ? kt : kt - 4;
        const uint32_t so = st * 8192;
        #pragma unroll
        for (int j = 0; j < 4; j++) {
            cpa16(saoff[j] + so, agp + akt * 64 + j * 8);
            cpa16(sboff[j] + so, bgp + bkt * 64 + j * 8);
        }
        CP_COMMIT();
    }

    int sbuf = 0;                         // stage buffer index (mod 3)
    for (int it = 0; it < kmax; it++) {
        CP_WAIT1();
        __syncthreads();

        const int nst = it + NST - 1;
        if (nst < kmax) {
            const int nb = (sbuf + 2 >= NST) ? sbuf + 2 - NST : sbuf + 2;
            const int kt  = (z == 2) ? nst : ((nst < 4) ? nst : nst + 4);
            const int akt = (kt < 8) ? kt : kt - 8;
            const int bkt = (kt < 4) ? kt : kt - 4;
            const uint32_t so = nb * 8192;
            #pragma unroll
            for (int j = 0; j < 4; j++) {
                cpa16(saoff[j] + so, agp + akt * 64 + j * 8);
                cpa16(sboff[j] + so, bgp + bkt * 64 + j * 8);
            }
        }
        CP_COMMIT();

        const uint32_t so = sbuf * 8192;
        #pragma unroll
        for (int h = 0; h < 4; h++) {
            uint32_t af[2][4], bfr[2][4];
            ldm_x4(af[0][0], af[0][1], af[0][2], af[0][3], aaddr[0][h] + so);
            ldm_x4(af[1][0], af[1][1], af[1][2], af[1][3], aaddr[1][h] + so);
            ldm_x4(bfr[0][0], bfr[0][1], bfr[0][2], bfr[0][3], baddr[0][h] + so);
            ldm_x4(bfr[1][0], bfr[1][1], bfr[1][2], bfr[1][3], baddr[1][h] + so);
            #pragma unroll
            for (int f = 0; f < 2; f++) {
                #pragma unroll
                for (int g = 0; g < 2; g++) {
                    mma16816(acc[f][2 * g + 0], af[f], &bfr[g][0]);
                    mma16816(acc[f][2 * g + 1], af[f], &bfr[g][2]);
                }
            }
        }
        sbuf = (sbuf + 1 >= NST) ? 0 : sbuf + 1;
    }

    // epilogue: add bias, store fp32
    const int tg = lane >> 2;
    const int tc = (lane & 3) * 2;
    #pragma unroll
    for (int f = 0; f < 2; f++) {
        const int rbase = row0 + warp_m * 32 + f * 16 + tg;
        #pragma unroll
        for (int g = 0; g < 4; g++) {
            const int c = col0 + warp_n * 32 + g * 8 + tc;
            const float b0 = bias[c], b1 = bias[c + 1];
            float2 v0 = { acc[f][g][0] + b0, acc[f][g][1] + b1 };
            float2 v1 = { acc[f][g][2] + b0, acc[f][g][3] + b1 };
            *(float2*)&Cw[(size_t)rbase * D + c]       = v0;
            *(float2*)&Cw[(size_t)(rbase + 8) * D + c] = v1;
        }
    }
}

// ---------------------------------------------------------------------------
// Attention via rank-13 Taylor factorization of exp(q*k/16).
// One warp per token; lane owns 8 CONTIGUOUS elements (float4 loads/stores).
// ---------------------------------------------------------------------------
__global__ __launch_bounds__(128) void attn_kernel(float* __restrict__ out)
{
    const int lane = threadIdx.x & 31;
    const int t = blockIdx.x * 4 + (threadIdx.x >> 5);
    const int base = t * D;
    const int eb = base + lane * 8;
    const float s = 1.0f / 16.0f;

    float4 k4a = *(const float4*)&g_K[eb];
    float4 k4b = *(const float4*)&g_K[eb + 4];
    float4 v4a = *(const float4*)&g_V[eb];
    float4 v4b = *(const float4*)&g_V[eb + 4];
    float4 q4a = *(const float4*)&g_Q[eb];
    float4 q4b = *(const float4*)&g_Q[eb + 4];

    float kv[8] = { k4a.x * s, k4a.y * s, k4a.z * s, k4a.w * s,
                    k4b.x * s, k4b.y * s, k4b.z * s, k4b.w * s };
    float vv[8] = { v4a.x, v4a.y, v4a.z, v4a.w, v4b.x, v4b.y, v4b.z, v4b.w };
    float qv[8] = { q4a.x, q4a.y, q4a.z, q4a.w, q4b.x, q4b.y, q4b.z, q4b.w };

    float m[13], M[13];
    #pragma unroll
    for (int n = 0; n < 13; n++) { m[n] = 0.f; M[n] = 0.f; }
    #pragma unroll
    for (int u = 0; u < 8; u++) {
        const float k1 = kv[u], v1 = vv[u];
        M[0] += v1;
        float kp = k1;
        m[1] += kp; M[1] += kp * v1;
        #pragma unroll
        for (int n = 2; n <= 12; n++) {
            kp *= k1;
            m[n] += kp;
            M[n] += kp * v1;
        }
    }
    m[0] = 8.0f;

    #pragma unroll
    for (int off = 16; off; off >>= 1) {
        #pragma unroll
        for (int n = 0; n < 13; n++) {
            m[n] += __shfl_xor_sync(0xFFFFFFFFu, m[n], off);
            M[n] += __shfl_xor_sync(0xFFFFFFFFu, M[n], off);
        }
    }

    const float invf[13] = {
        1.f, 1.f, 0.5f, 1.f/6.f, 1.f/24.f, 1.f/120.f, 1.f/720.f,
        1.f/5040.f, 1.f/40320.f, 1.f/362880.f, 1.f/3628800.f,
        1.f/39916800.f, 1.f/479001600.f };
    #pragma unroll
    for (int n = 2; n < 13; n++) { m[n] *= invf[n]; M[n] *= invf[n]; }

    float res[8];
    #pragma unroll
    for (int u = 0; u < 8; u++) {
        const float q = qv[u];
        float num = M[12], den = m[12];
        #pragma unroll
        for (int n = 11; n >= 0; n--) {
            num = num * q + M[n];
            den = den * q + m[n];
        }
        res[u] = __fdividef(num, den);
    }
    *(float4*)&out[eb]     = make_float4(res[0], res[1], res[2], res[3]);
    *(float4*)&out[eb + 4] = make_float4(res[4], res[5], res[6], res[7]);
}

// ---------------------------------------------------------------------------
// Launch. Inputs: x, Wq, bq, Wk, bk, Wv, bv. Output fp32 [2,1024,256].
// ---------------------------------------------------------------------------
extern "C" void kernel_launch(void* const* d_in, const int* in_sizes, int n_in,
                              void* d_out, int out_size)
{
    const float* x  = (const float*)d_in[0];
    const float* Wq = (const float*)d_in[1];
    const float* bq = (const float*)d_in[2];
    const float* Wk = (const float*)d_in[3];
    const float* bk = (const float*)d_in[4];
    const float* Wv = (const float*)d_in[5];
    const float* bv = (const float*)d_in[6];
    float* out = (float*)d_out;

    convert_all<<<704, 256>>>((const float4*)x, (const float4*)Wq,
                              (const float4*)Wk, (const float4*)Wv);
    dim3 ggrid(BT / 64, D / 64, 3);   // 32 x 4 x 3 = 384 CTAs
    mma_gemm<<<ggrid, 128>>>(bq, bk, bv);
    attn_kernel<<<BT / 4, 128>>>(out);
}